// round 5
// baseline (speedup 1.0000x reference)
#include <cuda_runtime.h>
#include <math_constants.h>

#define N_PTS 65536
#define KNNK 54
#define GRIDD 16
#define NCELL 4096
#define CELLH 0.0625f
#define FBLK 1024    // featK: 1024 blocks x 64 threads

#define TWO_PI_F 6.28318530717958647692f
#define PI_F     3.14159265358979323846f
#define SQRT3_F  1.73205080756887729353f

// ---------------- scratch (static device memory; no allocation) ----------------
__device__ float4 d_sorted[N_PTS];
__device__ int d_cellStart[NCELL + 1];
__device__ int d_cellPtr[NCELL];
__device__ int d_cnt[NCELL];
__device__ unsigned long long d_key[KNNK * N_PTS];  // transposed: [slot][point]
__device__ float d_h[N_PTS * KNNK * 10];            // transposed: [ch][p]
__device__ float d_part[FBLK * 20];
__device__ float d_bn[20];

__device__ __forceinline__ int cellCoord(float v) {
    int c = (int)floorf(v * 16.0f);
    c = c < 0 ? 0 : c;
    return c > (GRIDD - 1) ? (GRIDD - 1) : c;
}

// XLA-style sum of squares: ((x*x + y*y) + z*z), separate mul/add, round-to-nearest
__device__ __forceinline__ float sumsq_rn(float x, float y, float z) {
    return __fadd_rn(__fadd_rn(__fmul_rn(x, x), __fmul_rn(y, y)), __fmul_rn(z, z));
}

// cuBLAS-style K=3 dot: ascending-k fma chain
__device__ __forceinline__ float dot3_fma(float ax, float ay, float az,
                                          float bx, float by, float bz) {
    return __fmaf_rn(az, bz, __fmaf_rn(ay, by, __fmul_rn(ax, bx)));
}

// order-preserving float->uint map (no NaNs in use)
__device__ __forceinline__ unsigned mapf(float d) {
    unsigned u = __float_as_uint(d);
    return (u & 0x80000000u) ? ~u : (u | 0x80000000u);
}
__device__ __forceinline__ float unmapf(unsigned m) {
    unsigned u = (m & 0x80000000u) ? (m & 0x7FFFFFFFu) : ~m;
    return __uint_as_float(u);
}

// ---------------- grid build ----------------
__global__ void countK(const float* __restrict__ c) {
    int i = blockIdx.x * blockDim.x + threadIdx.x;
    if (i >= N_PTS) return;
    int cx = cellCoord(c[3 * i]);
    int cy = cellCoord(c[3 * i + 1]);
    int cz = cellCoord(c[3 * i + 2]);
    atomicAdd(&d_cnt[(cz * GRIDD + cy) * GRIDD + cx], 1);
}

__global__ __launch_bounds__(1024) void scanK() {
    __shared__ int s[1024];
    int t = threadIdx.x;
    int v0 = d_cnt[4 * t], v1 = d_cnt[4 * t + 1], v2 = d_cnt[4 * t + 2], v3 = d_cnt[4 * t + 3];
    int tot = v0 + v1 + v2 + v3;
    s[t] = tot;
    __syncthreads();
    for (int off = 1; off < 1024; off <<= 1) {
        int x = (t >= off) ? s[t - off] : 0;
        __syncthreads();
        s[t] += x;
        __syncthreads();
    }
    int excl = s[t] - tot;
    d_cellStart[4 * t] = excl;
    d_cellStart[4 * t + 1] = excl + v0;
    d_cellStart[4 * t + 2] = excl + v0 + v1;
    d_cellStart[4 * t + 3] = excl + v0 + v1 + v2;
    d_cellPtr[4 * t] = excl;
    d_cellPtr[4 * t + 1] = excl + v0;
    d_cellPtr[4 * t + 2] = excl + v0 + v1;
    d_cellPtr[4 * t + 3] = excl + v0 + v1 + v2;
    if (t == 1023) d_cellStart[NCELL] = s[1023];
}

__global__ void scatterK(const float* __restrict__ c) {
    int i = blockIdx.x * blockDim.x + threadIdx.x;
    if (i >= N_PTS) return;
    float x = c[3 * i], y = c[3 * i + 1], z = c[3 * i + 2];
    int cid = (cellCoord(z) * GRIDD + cellCoord(y)) * GRIDD + cellCoord(x);
    int pos = atomicAdd(&d_cellPtr[cid], 1);
    d_sorted[pos] = make_float4(x, y, z, __int_as_float(i));
}

// ---------------- KNN: register-resident top-54, box culling, exact-gap stop ----------------
__global__ __launch_bounds__(128) void knnK() {
    int t = blockIdx.x * 128 + threadIdx.x;
    float4 q = d_sorted[t];
    int qi = __float_as_int(q.w);
    float qx = q.x, qy = q.y, qz = q.z;
    float qsq = sumsq_rn(qx, qy, qz);
    int cx = cellCoord(qx), cy = cellCoord(qy), cz = cellCoord(qz);

    const unsigned long long INIT =
        ((unsigned long long)0xFF800000u << 32) | 0x7FFFFFFFu;  // (+inf, INT_MAX)
    unsigned long long kv[KNNK];
#pragma unroll
    for (int j = 0; j < KNNK; j++) kv[j] = INIT;
    unsigned long long wkey = INIT;
    int ws = 0;
    float worst_d = CUDART_INF_F;

    int maxm = cx; if (GRIDD - 1 - cx > maxm) maxm = GRIDD - 1 - cx;
    if (cy > maxm) maxm = cy; if (GRIDD - 1 - cy > maxm) maxm = GRIDD - 1 - cy;
    if (cz > maxm) maxm = cz; if (GRIDD - 1 - cz > maxm) maxm = GRIDD - 1 - cz;

    for (int m = 0;; m++) {
        int zlo = cz - m < 0 ? 0 : cz - m;
        int zhi = cz + m > GRIDD - 1 ? GRIDD - 1 : cz + m;
        for (int z = zlo; z <= zhi; z++) {
            int adz = z - cz; adz = adz < 0 ? -adz : adz;
            float lo = (float)z * CELLH, hi = lo + CELLH;
            float dz = fmaxf(0.0f, fmaxf(lo - qz, qz - hi));
            float dz2 = dz * dz;
            int ylo = cy - m < 0 ? 0 : cy - m;
            int yhi = cy + m > GRIDD - 1 ? GRIDD - 1 : cy + m;
            for (int y = ylo; y <= yhi; y++) {
                int ady = y - cy; ady = ady < 0 ? -ady : ady;
                float lyo = (float)y * CELLH, lyh = lyo + CELLH;
                float dy = fmaxf(0.0f, fmaxf(lyo - qy, qy - lyh));
                float dyz2 = dz2 + dy * dy;
                if (dyz2 > worst_d + 4e-6f) continue;   // whole row of cells culled
                int xlo = cx - m < 0 ? 0 : cx - m;
                int xhi = cx + m > GRIDD - 1 ? GRIDD - 1 : cx + m;
                for (int x = xlo; x <= xhi; x++) {
                    int adx = x - cx; adx = adx < 0 ? -adx : adx;
                    int cheb = adx > ady ? adx : ady;
                    if (adz > cheb) cheb = adz;
                    if (cheb != m) continue;
                    float lxo = (float)x * CELLH, lxh = lxo + CELLH;
                    float dx = fmaxf(0.0f, fmaxf(lxo - qx, qx - lxh));
                    if (dyz2 + dx * dx > worst_d + 4e-6f) continue;   // cell culled
                    int cid = (z * GRIDD + y) * GRIDD + x;
                    int s = d_cellStart[cid], e = d_cellStart[cid + 1];
                    for (int p = s; p < e; p++) {
                        float4 pt = d_sorted[p];
                        float psq = sumsq_rn(pt.x, pt.y, pt.z);
                        float dot = dot3_fma(qx, qy, qz, pt.x, pt.y, pt.z);
                        float d = __fsub_rn(__fadd_rn(qsq, psq), __fmul_rn(2.0f, dot));
                        unsigned pi = __float_as_uint(pt.w);
                        unsigned long long nk = ((unsigned long long)mapf(d) << 32) | pi;
                        if (nk < wkey) {
                            unsigned long long bv = 0ULL;
                            int bs = 0;
#pragma unroll
                            for (int j = 0; j < KNNK; j++) {
                                if (j == ws) kv[j] = nk;
                                if (kv[j] > bv) { bv = kv[j]; bs = j; }
                            }
                            ws = bs; wkey = bv;
                            worst_d = unmapf((unsigned)(wkey >> 32));
                        }
                    }
                }
            }
        }
        if (m >= maxm) break;
        // exact gap from q to the unprocessed region (outside the [c-m, c+m] cube)
        float g = CUDART_INF_F;
        if (cx - m > 0)         g = fminf(g, qx - (float)(cx - m) * CELLH);
        if (cx + m < GRIDD - 1) g = fminf(g, (float)(cx + m + 1) * CELLH - qx);
        if (cy - m > 0)         g = fminf(g, qy - (float)(cy - m) * CELLH);
        if (cy + m < GRIDD - 1) g = fminf(g, (float)(cy + m + 1) * CELLH - qy);
        if (cz - m > 0)         g = fminf(g, qz - (float)(cz - m) * CELLH);
        if (cz + m < GRIDD - 1) g = fminf(g, (float)(cz + m + 1) * CELLH - qz);
        if (worst_d + 4e-6f < g * g) break;
    }
#pragma unroll
    for (int j = 0; j < KNNK; j++) d_key[(size_t)j * N_PTS + qi] = kv[j];
}

// ---------------- features + layer1 + BN partial sums ----------------
__global__ __launch_bounds__(64) void featK(const float* __restrict__ cen,
                                            const float* __restrict__ W1,
                                            const float* __restrict__ b1) {
    __shared__ float sW1[100], sb1[10];
    __shared__ float sRho[54 * 64];
    __shared__ float sPhi[54 * 64];
    __shared__ int sPermA[54 * 64];
    __shared__ float sRed[20];
    int* sPermB = (int*)sRho;   // rho dead after rho-rank
    int* sIdx = (int*)sPhi;     // phi dead after phi-rank

    int tid = threadIdx.x;
    for (int i = tid; i < 100; i += 64) sW1[i] = W1[i];
    if (tid < 10) sb1[tid] = b1[tid];
    __syncthreads();

    int p = blockIdx.x * 64 + tid;
    float qx = cen[3 * p], qy = cen[3 * p + 1], qz = cen[3 * p + 2];

    auto keyAt = [&](int i) -> unsigned long long {
        return d_key[(size_t)i * N_PTS + p];   // coalesced across lanes
    };

    // phase A: per-slot rho & phi keys (order-independent per neighbor)
    for (int j = 0; j < 54; j++) {
        int nb = (int)(keyAt(j) & 0xFFFFFFFFull);
        float x = __fsub_rn(cen[3 * nb], qx);
        float y = __fsub_rn(cen[3 * nb + 1], qy);
        float z = __fsub_rn(cen[3 * nb + 2], qz);
        float rx = __fmaf_rn(z, -0.5f,    __fmaf_rn(y, 0.7071f, __fmul_rn(x,  0.5f)));
        float ry = __fmaf_rn(z,  0.5f,    __fmaf_rn(y, 0.7071f, __fmul_rn(x, -0.5f)));
        float rz = __fmaf_rn(z,  0.7071f, __fmul_rn(x, 0.7071f));
        sRho[j * 64 + tid] = __fsqrt_rn(sumsq_rn(rx, ry, rz));
        sPhi[j * 64 + tid] = __fadd_rn(__fdiv_rn(atan2f(ry, rx), TWO_PI_F), 0.5f);
    }

    // rho rank-sort; comparator lex(rho, key64) == stable rho-sort of (d,idx)-asc order
    for (int j = 0; j < 54; j++) {
        float kj = sRho[j * 64 + tid];
        int r = 0;
#pragma unroll
        for (int i = 0; i < 54; i++) {
            float ki = sRho[i * 64 + tid];
            if (ki < kj) r++;
            else if (ki == kj && i != j && keyAt(i) < keyAt(j)) r++;   // rare tie
        }
        sPermA[r * 64 + tid] = j;
    }

    // stable phi rank-sort within segments [0,9) [9,27) [27,54)
#define PHI_SEG(A, B)                                                        \
    for (int pos = (A); pos < (B); pos++) {                                  \
        int sl = sPermA[pos * 64 + tid];                                     \
        float kp = sPhi[sl * 64 + tid];                                      \
        int r = 0;                                                           \
        _Pragma("unroll")                                                    \
        for (int i = (A); i < (B); i++) {                                    \
            int si = sPermA[i * 64 + tid];                                   \
            float ki = sPhi[si * 64 + tid];                                  \
            r += (ki < kp || (ki == kp && i < pos)) ? 1 : 0;                 \
        }                                                                    \
        sPermB[((A) + r) * 64 + tid] = sl;                                   \
    }
    PHI_SEG(0, 9)
    PHI_SEG(9, 27)
    PHI_SEG(27, 54)
#undef PHI_SEG

    // materialize sorted neighbor indices (destroys phi)
    for (int t = 0; t < 54; t++) {
        int sl = sPermB[t * 64 + tid];
        sIdx[t * 64 + tid] = (int)(keyAt(sl) & 0xFFFFFFFFull);
    }

    // pre-pass: bad mask, pm (sign from triangle 0), first good triangle
    unsigned long long badm = 0ULL;
    float pm = 1.0f;
    int first = -1;
    for (int t = 0; t < 54; t++) {
        int base, len;
        if (t < 9) { base = 0; len = 9; }
        else if (t < 27) { base = 9; len = 18; }
        else { base = 27; len = 27; }
        int loc = t - base + 1;
        int nt = base + (loc == len ? 0 : loc);
        int na = sIdx[t * 64 + tid], nb = sIdx[nt * 64 + tid];
        float e1x = __fsub_rn(cen[3 * na], qx);
        float e1y = __fsub_rn(cen[3 * na + 1], qy);
        float e1z = __fsub_rn(cen[3 * na + 2], qz);
        float e2x = __fsub_rn(cen[3 * nb], qx);
        float e2y = __fsub_rn(cen[3 * nb + 1], qy);
        float e2z = __fsub_rn(cen[3 * nb + 2], qz);
        float nx = __fsub_rn(__fmul_rn(e1y, e2z), __fmul_rn(e1z, e2y));
        float ny = __fsub_rn(__fmul_rn(e1z, e2x), __fmul_rn(e1x, e2z));
        float nz = __fsub_rn(__fmul_rn(e1x, e2y), __fmul_rn(e1y, e2x));
        float nl = __fsqrt_rn(sumsq_rn(nx, ny, nz));
        bool bad = (nl == 0.0f);
        if (t == 0) {
            float ux = bad ? 0.0f : __fdiv_rn(nx, nl);
            pm = (ux > 0.0f) ? 1.0f : -1.0f;
        }
        if (bad) badm |= (1ULL << t);
        else if (first < 0) first = t;
    }
    if (first < 0) first = 0;

    // triangle evaluator (bit-identical expressions)
    auto evalTri = [&](int t, float& ux, float& uy, float& uz,
                       float& ccx, float& ccy, float& ccz, float& pos) {
        int base, len;
        if (t < 9) { base = 0; len = 9; }
        else if (t < 27) { base = 9; len = 18; }
        else { base = 27; len = 27; }
        int loc = t - base + 1;
        int nt = base + (loc == len ? 0 : loc);
        int na = sIdx[t * 64 + tid], nb = sIdx[nt * 64 + tid];
        float e1x = __fsub_rn(cen[3 * na], qx);
        float e1y = __fsub_rn(cen[3 * na + 1], qy);
        float e1z = __fsub_rn(cen[3 * na + 2], qz);
        float e2x = __fsub_rn(cen[3 * nb], qx);
        float e2y = __fsub_rn(cen[3 * nb + 1], qy);
        float e2z = __fsub_rn(cen[3 * nb + 2], qz);
        float nx = __fsub_rn(__fmul_rn(e1y, e2z), __fmul_rn(e1z, e2y));
        float ny = __fsub_rn(__fmul_rn(e1z, e2x), __fmul_rn(e1x, e2z));
        float nz = __fsub_rn(__fmul_rn(e1x, e2y), __fmul_rn(e1y, e2x));
        float nl = __fsqrt_rn(sumsq_rn(nx, ny, nz));
        bool bad = (nl == 0.0f);
        if (bad) { ux = 0.0f; uy = 0.0f; uz = 0.0f; }
        else {
            ux = __fdiv_rn(nx, nl); uy = __fdiv_rn(ny, nl); uz = __fdiv_rn(nz, nl);
        }
        ux = __fmul_rn(ux, pm); uy = __fmul_rn(uy, pm); uz = __fmul_rn(uz, pm);
        ccx = __fdiv_rn(__fadd_rn(e1x, e2x), 3.0f);
        ccy = __fdiv_rn(__fadd_rn(e1y, e2y), 3.0f);
        ccz = __fdiv_rn(__fadd_rn(e1z, e2z), 3.0f);
        pos = __fdiv_rn(
            __fadd_rn(__fadd_rn(__fmul_rn(ux, ccx), __fmul_rn(uy, ccy)), __fmul_rn(uz, ccz)),
            SQRT3_F);
    };

    float fux, fuy, fuz, fcx, fcy, fcz, fpos;
    evalTri(first, fux, fuy, fuz, fcx, fcy, fcz, fpos);

    float s0[10], s1[10];
#pragma unroll
    for (int c = 0; c < 10; c++) { s0[c] = 0.0f; s1[c] = 0.0f; }

    for (int t = 0; t < 54; t++) {
        float ux, uy, uz, ccx, ccy, ccz, pos;
        evalTri(t, ux, uy, uz, ccx, ccy, ccz, pos);
        bool bad = ((badm >> t) & 1ULL) != 0ULL;

        float rho = __fsqrt_rn(sumsq_rn(ccx, ccy, ccz));
        float phi = __fadd_rn(__fdiv_rn(atan2f(ccy, ccx), TWO_PI_F), 0.5f);
        float theta;
        if (rho == 0.0f) theta = 0.0f;
        else {
            float r = __fdiv_rn(ccz, rho);
            r = fminf(1.0f, fmaxf(-1.0f, r));
            theta = __fdiv_rn(acosf(r), PI_F);
        }
        float f[10];
        f[0] = rho; f[1] = theta; f[2] = phi;
        f[3] = bad ? fux : ux; f[4] = bad ? fuy : uy; f[5] = bad ? fuz : uz;
        f[6] = bad ? fpos : pos;
        f[7] = bad ? fcx : ccx; f[8] = bad ? fcy : ccy; f[9] = bad ? fcz : ccz;

        int chBase = t * 10;
#pragma unroll
        for (int c = 0; c < 10; c++) {
            float acc = 0.0f;
#pragma unroll
            for (int k = 0; k < 10; k++) acc += f[k] * sW1[c * 10 + k];
            float h = acc + sb1[c];
            d_h[(size_t)(chBase + c) * N_PTS + p] = h;   // coalesced
            s0[c] += h;
            s1[c] += h * h;
        }
    }

    // block reduction: warp shuffle, then cross-warp via 20 smem floats
    int lane = tid & 31, wrp = tid >> 5;
#pragma unroll
    for (int v = 0; v < 20; v++) {
        float a = (v < 10) ? s0[v] : s1[v - 10];
#pragma unroll
        for (int off = 16; off > 0; off >>= 1) a += __shfl_down_sync(0xFFFFFFFFu, a, off);
        if (lane == 0) {
            if (wrp == 0) sRed[v] = a;
        }
        __syncthreads();
        if (lane == 0 && wrp == 1) sRed[v] += a;
        __syncthreads();
    }
    if (tid < 20) d_part[blockIdx.x * 20 + tid] = sRed[tid];
}

// ---------------- BN finalize: warp-per-channel reduction over FBLK partials ----------------
__global__ __launch_bounds__(640) void bnK(const float* __restrict__ gamma,
                                           const float* __restrict__ beta) {
    __shared__ float S[20];
    int tid = threadIdx.x;
    int w = tid / 32, l = tid % 32;
    float a = 0.0f;
    for (int k = l; k < FBLK; k += 32) a += d_part[k * 20 + w];
#pragma unroll
    for (int off = 16; off > 0; off >>= 1) a += __shfl_down_sync(0xFFFFFFFFu, a, off);
    if (l == 0) S[w] = a;
    __syncthreads();
    if (tid < 10) {
        const double M = (double)N_PTS * 54.0;
        double mu = (double)S[tid] / M;
        double var = (double)S[tid + 10] / M - mu * mu;
        if (var < 0.0) var = 0.0;
        float sc = gamma[tid] * rsqrtf((float)var + 1e-5f);
        d_bn[tid] = sc;
        d_bn[10 + tid] = beta[tid] - (float)mu * sc;
    }
}

// ---------------- BN affine + relu + layer2 + sum over 54 ----------------
__global__ __launch_bounds__(256) void outK(const float* __restrict__ W2,
                                            const float* __restrict__ b2,
                                            float* __restrict__ out) {
    __shared__ float sa[10], sb[10], sW2[100], sb2[10];
    int tid = threadIdx.x;
    if (tid < 10) { sa[tid] = d_bn[tid]; sb[tid] = d_bn[10 + tid]; sb2[tid] = b2[tid]; }
    if (tid < 100) sW2[tid] = W2[tid];
    __syncthreads();

    int p = blockIdx.x * blockDim.x + tid;
    float acc[10];
#pragma unroll
    for (int c = 0; c < 10; c++) acc[c] = 0.0f;
    for (int t = 0; t < 54; t++) {
#pragma unroll
        for (int c = 0; c < 10; c++) {
            float v = d_h[(size_t)(t * 10 + c) * N_PTS + p] * sa[c] + sb[c];
            v = fmaxf(v, 0.0f);
            acc[c] += v;
        }
    }
#pragma unroll
    for (int c = 0; c < 10; c++) {
        float o = 54.0f * sb2[c];
#pragma unroll
        for (int j = 0; j < 10; j++) o += acc[j] * sW2[c * 10 + j];
        out[p * 10 + c] = o;
    }
}

// ---------------- launch ----------------
extern "C" void kernel_launch(void* const* d_in, const int* in_sizes, int n_in,
                              void* d_out, int out_size) {
    const float* center = (const float*)d_in[0];
    const float* W1 = (const float*)d_in[2];
    const float* b1 = (const float*)d_in[3];
    const float* gamma = (const float*)d_in[4];
    const float* beta = (const float*)d_in[5];
    const float* W2 = (const float*)d_in[6];
    const float* b2 = (const float*)d_in[7];
    float* out = (float*)d_out;

    void* cntPtr = nullptr;
    cudaGetSymbolAddress(&cntPtr, d_cnt);
    cudaMemsetAsync(cntPtr, 0, NCELL * sizeof(int), 0);   // memset node, not a kernel

    countK<<<256, 256>>>(center);
    scanK<<<1, 1024>>>();
    scatterK<<<256, 256>>>(center);
    knnK<<<512, 128>>>();                                  // 4th kernel launch -> ncu slot
    featK<<<FBLK, 64>>>(center, W1, b1);
    bnK<<<1, 640>>>(gamma, beta);
    outK<<<256, 256>>>(W2, b2, out);
}

// round 6
// speedup vs baseline: 1.4003x; 1.4003x over previous
#include <cuda_runtime.h>
#include <math_constants.h>

#define N_PTS 65536
#define KNNK 54
#define GRIDD 16
#define NCELL 4096
#define CELLH 0.0625f
#define FBLK 1024    // featK: 1024 blocks x 64 threads

#define TWO_PI_F 6.28318530717958647692f
#define PI_F     3.14159265358979323846f
#define SQRT3_F  1.73205080756887729353f

// ---------------- scratch (static device memory; no allocation) ----------------
__device__ float4 d_sorted[N_PTS];
__device__ int d_cellStart[NCELL + 1];
__device__ int d_cellPtr[NCELL];
__device__ int d_cnt[NCELL];
__device__ unsigned long long d_key[KNNK * N_PTS];  // transposed: [slot][point]
__device__ float d_h[N_PTS * KNNK * 10];            // transposed: [ch][p]
__device__ float d_part[FBLK * 20];
__device__ float d_bn[20];

// canonical (+,+,+) octant: 27 cell offsets sorted by min box distance
// groups: d2(h^2/16) = 0,1,2,3,9,10,11,18,19,27
__constant__ char4 c_ord[27] = {
    { 0, 0, 0, 0},
    { 1, 0, 0, 0}, { 0, 1, 0, 0}, { 0, 0, 1, 0},
    { 1, 1, 0, 0}, { 1, 0, 1, 0}, { 0, 1, 1, 0},
    { 1, 1, 1, 0},
    {-1, 0, 0, 0}, { 0,-1, 0, 0}, { 0, 0,-1, 0},
    {-1, 1, 0, 0}, {-1, 0, 1, 0}, { 1,-1, 0, 0},
    { 0,-1, 1, 0}, { 1, 0,-1, 0}, { 0, 1,-1, 0},
    {-1, 1, 1, 0}, { 1,-1, 1, 0}, { 1, 1,-1, 0},
    {-1,-1, 0, 0}, {-1, 0,-1, 0}, { 0,-1,-1, 0},
    {-1,-1, 1, 0}, {-1, 1,-1, 0}, { 1,-1,-1, 0},
    {-1,-1,-1, 0}
};

__device__ __forceinline__ int cellCoord(float v) {
    int c = (int)floorf(v * 16.0f);
    c = c < 0 ? 0 : c;
    return c > (GRIDD - 1) ? (GRIDD - 1) : c;
}

// XLA-style sum of squares: ((x*x + y*y) + z*z), separate mul/add, round-to-nearest
__device__ __forceinline__ float sumsq_rn(float x, float y, float z) {
    return __fadd_rn(__fadd_rn(__fmul_rn(x, x), __fmul_rn(y, y)), __fmul_rn(z, z));
}

// cuBLAS-style K=3 dot: ascending-k fma chain
__device__ __forceinline__ float dot3_fma(float ax, float ay, float az,
                                          float bx, float by, float bz) {
    return __fmaf_rn(az, bz, __fmaf_rn(ay, by, __fmul_rn(ax, bx)));
}

// order-preserving float->uint map (no NaNs in use)
__device__ __forceinline__ unsigned mapf(float d) {
    unsigned u = __float_as_uint(d);
    return (u & 0x80000000u) ? ~u : (u | 0x80000000u);
}
__device__ __forceinline__ float unmapf(unsigned m) {
    unsigned u = (m & 0x80000000u) ? (m & 0x7FFFFFFFu) : ~m;
    return __uint_as_float(u);
}

// ---------------- grid build ----------------
__global__ void countK(const float* __restrict__ c) {
    int i = blockIdx.x * blockDim.x + threadIdx.x;
    if (i >= N_PTS) return;
    int cx = cellCoord(c[3 * i]);
    int cy = cellCoord(c[3 * i + 1]);
    int cz = cellCoord(c[3 * i + 2]);
    atomicAdd(&d_cnt[(cz * GRIDD + cy) * GRIDD + cx], 1);
}

__global__ __launch_bounds__(1024) void scanK() {
    __shared__ int s[1024];
    int t = threadIdx.x;
    int v0 = d_cnt[4 * t], v1 = d_cnt[4 * t + 1], v2 = d_cnt[4 * t + 2], v3 = d_cnt[4 * t + 3];
    int tot = v0 + v1 + v2 + v3;
    s[t] = tot;
    __syncthreads();
    for (int off = 1; off < 1024; off <<= 1) {
        int x = (t >= off) ? s[t - off] : 0;
        __syncthreads();
        s[t] += x;
        __syncthreads();
    }
    int excl = s[t] - tot;
    d_cellStart[4 * t] = excl;
    d_cellStart[4 * t + 1] = excl + v0;
    d_cellStart[4 * t + 2] = excl + v0 + v1;
    d_cellStart[4 * t + 3] = excl + v0 + v1 + v2;
    d_cellPtr[4 * t] = excl;
    d_cellPtr[4 * t + 1] = excl + v0;
    d_cellPtr[4 * t + 2] = excl + v0 + v1;
    d_cellPtr[4 * t + 3] = excl + v0 + v1 + v2;
    if (t == 1023) d_cellStart[NCELL] = s[1023];
}

__global__ void scatterK(const float* __restrict__ c) {
    int i = blockIdx.x * blockDim.x + threadIdx.x;
    if (i >= N_PTS) return;
    float x = c[3 * i], y = c[3 * i + 1], z = c[3 * i + 2];
    int cid = (cellCoord(z) * GRIDD + cellCoord(y)) * GRIDD + cellCoord(x);
    int pos = atomicAdd(&d_cellPtr[cid], 1);
    d_sorted[pos] = make_float4(x, y, z, __int_as_float(i));
}

// ---------------- KNN: smem top-54, distance-ordered cells, fill-then-track ----------------
__global__ __launch_bounds__(64) void knnK() {
    __shared__ unsigned long long sKV[KNNK * 64];
    int tid = threadIdx.x;
    int t = blockIdx.x * 64 + tid;
    float4 q = d_sorted[t];
    int qi = __float_as_int(q.w);
    float qx = q.x, qy = q.y, qz = q.z;
    float qsq = sumsq_rn(qx, qy, qz);
    int cx = cellCoord(qx), cy = cellCoord(qy), cz = cellCoord(qz);

    int count = 0;
    unsigned long long wkey = 0xFFFFFFFFFFFFFFFFull;
    int ws = 0;
    float worst_d = CUDART_INF_F;

    auto processCell = [&](int cid) {
        int s = d_cellStart[cid], e = d_cellStart[cid + 1];
        for (int p = s; p < e; p++) {
            float4 pt = d_sorted[p];
            float psq = sumsq_rn(pt.x, pt.y, pt.z);
            float dot = dot3_fma(qx, qy, qz, pt.x, pt.y, pt.z);
            float d = __fsub_rn(__fadd_rn(qsq, psq), __fmul_rn(2.0f, dot));
            unsigned pi = __float_as_uint(pt.w);
            unsigned long long nk = ((unsigned long long)mapf(d) << 32) | pi;
            if (count < KNNK) {
                sKV[count * 64 + tid] = nk;
                count++;
                if (count == KNNK) {
                    unsigned long long bv = 0ULL; int bs = 0;
#pragma unroll
                    for (int j = 0; j < KNNK; j++) {
                        unsigned long long v = sKV[j * 64 + tid];
                        if (v > bv) { bv = v; bs = j; }
                    }
                    wkey = bv; ws = bs;
                    worst_d = unmapf((unsigned)(bv >> 32));
                }
            } else if (nk < wkey) {
                sKV[ws * 64 + tid] = nk;
                unsigned long long bv = 0ULL; int bs = 0;
#pragma unroll
                for (int j = 0; j < KNNK; j++) {
                    unsigned long long v = sKV[j * 64 + tid];
                    if (v > bv) { bv = v; bs = j; }
                }
                wkey = bv; ws = bs;
                worst_d = unmapf((unsigned)(bv >> 32));
            }
        }
    };

    // octant signs: which half of the cell is q in (near side first in canonical order)
    int sx = (qx > ((float)cx + 0.5f) * CELLH) ? 1 : -1;
    int sy = (qy > ((float)cy + 0.5f) * CELLH) ? 1 : -1;
    int sz = (qz > ((float)cz + 0.5f) * CELLH) ? 1 : -1;

    // phase 1: 27 cells (m<=1) in approximate box-distance order
#pragma unroll 1
    for (int o = 0; o < 27; o++) {
        char4 c = c_ord[o];
        int x = cx + sx * (int)c.x;
        int y = cy + sy * (int)c.y;
        int z = cz + sz * (int)c.z;
        if (((unsigned)x | (unsigned)y | (unsigned)z) > 15u) continue;
        // exact box-distance cull (no-op while filling: worst_d = inf)
        float dxx = fmaxf(0.0f, fmaxf((float)x * CELLH - qx, qx - ((float)x * CELLH + CELLH)));
        float dyy = fmaxf(0.0f, fmaxf((float)y * CELLH - qy, qy - ((float)y * CELLH + CELLH)));
        float dzz = fmaxf(0.0f, fmaxf((float)z * CELLH - qz, qz - ((float)z * CELLH + CELLH)));
        if (dxx * dxx + dyy * dyy + dzz * dzz > worst_d + 4e-6f) continue;
        processCell((z * GRIDD + y) * GRIDD + x);
    }

    // gap to the region outside the 3x3x3 cube
    {
        float g = CUDART_INF_F;
        if (cx - 1 > 0)         g = fminf(g, qx - (float)(cx - 1) * CELLH);
        if (cx + 1 < GRIDD - 1) g = fminf(g, (float)(cx + 2) * CELLH - qx);
        if (cy - 1 > 0)         g = fminf(g, qy - (float)(cy - 1) * CELLH);
        if (cy + 1 < GRIDD - 1) g = fminf(g, (float)(cy + 2) * CELLH - qy);
        if (cz - 1 > 0)         g = fminf(g, qz - (float)(cz - 1) * CELLH);
        if (cz + 1 < GRIDD - 1) g = fminf(g, (float)(cz + 2) * CELLH - qz);
        if (worst_d + 4e-6f < g * g) goto done;
    }

    // phase 2: rings m >= 2 (rare)
    {
        int maxm = cx; if (GRIDD - 1 - cx > maxm) maxm = GRIDD - 1 - cx;
        if (cy > maxm) maxm = cy; if (GRIDD - 1 - cy > maxm) maxm = GRIDD - 1 - cy;
        if (cz > maxm) maxm = cz; if (GRIDD - 1 - cz > maxm) maxm = GRIDD - 1 - cz;

        for (int m = 2; m <= maxm; m++) {
            int zlo = cz - m < 0 ? 0 : cz - m;
            int zhi = cz + m > GRIDD - 1 ? GRIDD - 1 : cz + m;
            for (int z = zlo; z <= zhi; z++) {
                int adz = z - cz; adz = adz < 0 ? -adz : adz;
                float lo = (float)z * CELLH, hi = lo + CELLH;
                float dz = fmaxf(0.0f, fmaxf(lo - qz, qz - hi));
                float dz2 = dz * dz;
                int ylo = cy - m < 0 ? 0 : cy - m;
                int yhi = cy + m > GRIDD - 1 ? GRIDD - 1 : cy + m;
                for (int y = ylo; y <= yhi; y++) {
                    int ady = y - cy; ady = ady < 0 ? -ady : ady;
                    float lyo = (float)y * CELLH, lyh = lyo + CELLH;
                    float dy = fmaxf(0.0f, fmaxf(lyo - qy, qy - lyh));
                    float dyz2 = dz2 + dy * dy;
                    if (dyz2 > worst_d + 4e-6f) continue;
                    int xlo = cx - m < 0 ? 0 : cx - m;
                    int xhi = cx + m > GRIDD - 1 ? GRIDD - 1 : cx + m;
                    for (int x = xlo; x <= xhi; x++) {
                        int adx = x - cx; adx = adx < 0 ? -adx : adx;
                        int cheb = adx > ady ? adx : ady;
                        if (adz > cheb) cheb = adz;
                        if (cheb != m) continue;
                        float lxo = (float)x * CELLH, lxh = lxo + CELLH;
                        float dx = fmaxf(0.0f, fmaxf(lxo - qx, qx - lxh));
                        if (dyz2 + dx * dx > worst_d + 4e-6f) continue;
                        processCell((z * GRIDD + y) * GRIDD + x);
                    }
                }
            }
            // exact gap from q to the unprocessed region (outside [c-m, c+m] cube)
            float g = CUDART_INF_F;
            if (cx - m > 0)         g = fminf(g, qx - (float)(cx - m) * CELLH);
            if (cx + m < GRIDD - 1) g = fminf(g, (float)(cx + m + 1) * CELLH - qx);
            if (cy - m > 0)         g = fminf(g, qy - (float)(cy - m) * CELLH);
            if (cy + m < GRIDD - 1) g = fminf(g, (float)(cy + m + 1) * CELLH - qy);
            if (cz - m > 0)         g = fminf(g, qz - (float)(cz - m) * CELLH);
            if (cz + m < GRIDD - 1) g = fminf(g, (float)(cz + m + 1) * CELLH - qz);
            if (worst_d + 4e-6f < g * g) break;
        }
    }

done:
#pragma unroll
    for (int j = 0; j < KNNK; j++) d_key[(size_t)j * N_PTS + qi] = sKV[j * 64 + tid];
}

// ---------------- features + layer1 + BN partial sums ----------------
__global__ __launch_bounds__(64) void featK(const float* __restrict__ cen,
                                            const float* __restrict__ W1,
                                            const float* __restrict__ b1) {
    __shared__ float sW1[100], sb1[10];
    __shared__ float sRho[54 * 64];
    __shared__ float sPhi[54 * 64];
    __shared__ unsigned char sPermA[54 * 64];
    __shared__ float sRed[20];
    unsigned char* sPermB = (unsigned char*)sRho;   // rho dead after rho-rank
    int* sIdx = (int*)sPhi;                         // phi dead after phi-rank

    int tid = threadIdx.x;
    for (int i = tid; i < 100; i += 64) sW1[i] = W1[i];
    if (tid < 10) sb1[tid] = b1[tid];
    __syncthreads();

    int p = blockIdx.x * 64 + tid;
    float qx = cen[3 * p], qy = cen[3 * p + 1], qz = cen[3 * p + 2];

    auto keyAt = [&](int i) -> unsigned long long {
        return d_key[(size_t)i * N_PTS + p];   // coalesced across lanes
    };

    // phase A: per-slot rho & phi keys (order-independent per neighbor)
    for (int j = 0; j < 54; j++) {
        int nb = (int)(keyAt(j) & 0xFFFFFFFFull);
        float x = __fsub_rn(cen[3 * nb], qx);
        float y = __fsub_rn(cen[3 * nb + 1], qy);
        float z = __fsub_rn(cen[3 * nb + 2], qz);
        float rx = __fmaf_rn(z, -0.5f,    __fmaf_rn(y, 0.7071f, __fmul_rn(x,  0.5f)));
        float ry = __fmaf_rn(z,  0.5f,    __fmaf_rn(y, 0.7071f, __fmul_rn(x, -0.5f)));
        float rz = __fmaf_rn(z,  0.7071f, __fmul_rn(x, 0.7071f));
        sRho[j * 64 + tid] = __fsqrt_rn(sumsq_rn(rx, ry, rz));
        sPhi[j * 64 + tid] = __fadd_rn(__fdiv_rn(atan2f(ry, rx), TWO_PI_F), 0.5f);
    }

    // rho rank-sort; comparator lex(rho, key64) == stable rho-sort of (d,idx)-asc order
    for (int j = 0; j < 54; j++) {
        float kj = sRho[j * 64 + tid];
        int r = 0;
#pragma unroll
        for (int i = 0; i < 54; i++) {
            float ki = sRho[i * 64 + tid];
            if (ki < kj) r++;
            else if (ki == kj && i != j && keyAt(i) < keyAt(j)) r++;   // rare tie
        }
        sPermA[r * 64 + tid] = (unsigned char)j;
    }

    // stable phi rank-sort within segments [0,9) [9,27) [27,54)
#define PHI_SEG(A, B)                                                        \
    for (int pos = (A); pos < (B); pos++) {                                  \
        int sl = sPermA[pos * 64 + tid];                                     \
        float kp = sPhi[sl * 64 + tid];                                      \
        int r = 0;                                                           \
        _Pragma("unroll")                                                    \
        for (int i = (A); i < (B); i++) {                                    \
            int si = sPermA[i * 64 + tid];                                   \
            float ki = sPhi[si * 64 + tid];                                  \
            r += (ki < kp || (ki == kp && i < pos)) ? 1 : 0;                 \
        }                                                                    \
        sPermB[((A) + r) * 64 + tid] = (unsigned char)sl;                    \
    }
    PHI_SEG(0, 9)
    PHI_SEG(9, 27)
    PHI_SEG(27, 54)
#undef PHI_SEG

    // materialize sorted neighbor indices (destroys phi)
    int tmpIdx[54];
#pragma unroll
    for (int t = 0; t < 54; t++) {
        int sl = sPermB[t * 64 + tid];
        tmpIdx[t] = (int)(keyAt(sl) & 0xFFFFFFFFull);
    }
    __syncwarp();
#pragma unroll
    for (int t = 0; t < 54; t++) sIdx[t * 64 + tid] = tmpIdx[t];

    // pre-pass: bad mask, pm (sign from triangle 0), first good triangle
    unsigned long long badm = 0ULL;
    float pm = 1.0f;
    int first = -1;
    for (int t = 0; t < 54; t++) {
        int base, len;
        if (t < 9) { base = 0; len = 9; }
        else if (t < 27) { base = 9; len = 18; }
        else { base = 27; len = 27; }
        int loc = t - base + 1;
        int nt = base + (loc == len ? 0 : loc);
        int na = sIdx[t * 64 + tid], nb = sIdx[nt * 64 + tid];
        float e1x = __fsub_rn(cen[3 * na], qx);
        float e1y = __fsub_rn(cen[3 * na + 1], qy);
        float e1z = __fsub_rn(cen[3 * na + 2], qz);
        float e2x = __fsub_rn(cen[3 * nb], qx);
        float e2y = __fsub_rn(cen[3 * nb + 1], qy);
        float e2z = __fsub_rn(cen[3 * nb + 2], qz);
        float nx = __fsub_rn(__fmul_rn(e1y, e2z), __fmul_rn(e1z, e2y));
        float ny = __fsub_rn(__fmul_rn(e1z, e2x), __fmul_rn(e1x, e2z));
        float nz = __fsub_rn(__fmul_rn(e1x, e2y), __fmul_rn(e1y, e2x));
        float nl = __fsqrt_rn(sumsq_rn(nx, ny, nz));
        bool bad = (nl == 0.0f);
        if (t == 0) {
            float ux = bad ? 0.0f : __fdiv_rn(nx, nl);
            pm = (ux > 0.0f) ? 1.0f : -1.0f;
        }
        if (bad) badm |= (1ULL << t);
        else if (first < 0) first = t;
    }
    if (first < 0) first = 0;

    // triangle evaluator (bit-identical expressions)
    auto evalTri = [&](int t, float& ux, float& uy, float& uz,
                       float& ccx, float& ccy, float& ccz, float& pos) {
        int base, len;
        if (t < 9) { base = 0; len = 9; }
        else if (t < 27) { base = 9; len = 18; }
        else { base = 27; len = 27; }
        int loc = t - base + 1;
        int nt = base + (loc == len ? 0 : loc);
        int na = sIdx[t * 64 + tid], nb = sIdx[nt * 64 + tid];
        float e1x = __fsub_rn(cen[3 * na], qx);
        float e1y = __fsub_rn(cen[3 * na + 1], qy);
        float e1z = __fsub_rn(cen[3 * na + 2], qz);
        float e2x = __fsub_rn(cen[3 * nb], qx);
        float e2y = __fsub_rn(cen[3 * nb + 1], qy);
        float e2z = __fsub_rn(cen[3 * nb + 2], qz);
        float nx = __fsub_rn(__fmul_rn(e1y, e2z), __fmul_rn(e1z, e2y));
        float ny = __fsub_rn(__fmul_rn(e1z, e2x), __fmul_rn(e1x, e2z));
        float nz = __fsub_rn(__fmul_rn(e1x, e2y), __fmul_rn(e1y, e2x));
        float nl = __fsqrt_rn(sumsq_rn(nx, ny, nz));
        bool bad = (nl == 0.0f);
        if (bad) { ux = 0.0f; uy = 0.0f; uz = 0.0f; }
        else {
            ux = __fdiv_rn(nx, nl); uy = __fdiv_rn(ny, nl); uz = __fdiv_rn(nz, nl);
        }
        ux = __fmul_rn(ux, pm); uy = __fmul_rn(uy, pm); uz = __fmul_rn(uz, pm);
        ccx = __fdiv_rn(__fadd_rn(e1x, e2x), 3.0f);
        ccy = __fdiv_rn(__fadd_rn(e1y, e2y), 3.0f);
        ccz = __fdiv_rn(__fadd_rn(e1z, e2z), 3.0f);
        pos = __fdiv_rn(
            __fadd_rn(__fadd_rn(__fmul_rn(ux, ccx), __fmul_rn(uy, ccy)), __fmul_rn(uz, ccz)),
            SQRT3_F);
    };

    float fux, fuy, fuz, fcx, fcy, fcz, fpos;
    evalTri(first, fux, fuy, fuz, fcx, fcy, fcz, fpos);

    float s0[10], s1[10];
#pragma unroll
    for (int c = 0; c < 10; c++) { s0[c] = 0.0f; s1[c] = 0.0f; }

    for (int t = 0; t < 54; t++) {
        float ux, uy, uz, ccx, ccy, ccz, pos;
        evalTri(t, ux, uy, uz, ccx, ccy, ccz, pos);
        bool bad = ((badm >> t) & 1ULL) != 0ULL;

        float rho = __fsqrt_rn(sumsq_rn(ccx, ccy, ccz));
        float phi = __fadd_rn(__fdiv_rn(atan2f(ccy, ccx), TWO_PI_F), 0.5f);
        float theta;
        if (rho == 0.0f) theta = 0.0f;
        else {
            float r = __fdiv_rn(ccz, rho);
            r = fminf(1.0f, fmaxf(-1.0f, r));
            theta = __fdiv_rn(acosf(r), PI_F);
        }
        float f[10];
        f[0] = rho; f[1] = theta; f[2] = phi;
        f[3] = bad ? fux : ux; f[4] = bad ? fuy : uy; f[5] = bad ? fuz : uz;
        f[6] = bad ? fpos : pos;
        f[7] = bad ? fcx : ccx; f[8] = bad ? fcy : ccy; f[9] = bad ? fcz : ccz;

        int chBase = t * 10;
#pragma unroll
        for (int c = 0; c < 10; c++) {
            float acc = 0.0f;
#pragma unroll
            for (int k = 0; k < 10; k++) acc += f[k] * sW1[c * 10 + k];
            float h = acc + sb1[c];
            d_h[(size_t)(chBase + c) * N_PTS + p] = h;   // coalesced
            s0[c] += h;
            s1[c] += h * h;
        }
    }

    // block reduction: warp shuffle, then cross-warp via 20 smem floats
    int lane = tid & 31, wrp = tid >> 5;
#pragma unroll
    for (int v = 0; v < 20; v++) {
        float a = (v < 10) ? s0[v] : s1[v - 10];
#pragma unroll
        for (int off = 16; off > 0; off >>= 1) a += __shfl_down_sync(0xFFFFFFFFu, a, off);
        if (lane == 0) {
            if (wrp == 0) sRed[v] = a;
        }
        __syncthreads();
        if (lane == 0 && wrp == 1) sRed[v] += a;
        __syncthreads();
    }
    if (tid < 20) d_part[blockIdx.x * 20 + tid] = sRed[tid];
}

// ---------------- BN finalize: warp-per-channel reduction over FBLK partials ----------------
__global__ __launch_bounds__(640) void bnK(const float* __restrict__ gamma,
                                           const float* __restrict__ beta) {
    __shared__ float S[20];
    int tid = threadIdx.x;
    int w = tid / 32, l = tid % 32;
    float a = 0.0f;
    for (int k = l; k < FBLK; k += 32) a += d_part[k * 20 + w];
#pragma unroll
    for (int off = 16; off > 0; off >>= 1) a += __shfl_down_sync(0xFFFFFFFFu, a, off);
    if (l == 0) S[w] = a;
    __syncthreads();
    if (tid < 10) {
        const double M = (double)N_PTS * 54.0;
        double mu = (double)S[tid] / M;
        double var = (double)S[tid + 10] / M - mu * mu;
        if (var < 0.0) var = 0.0;
        float sc = gamma[tid] * rsqrtf((float)var + 1e-5f);
        d_bn[tid] = sc;
        d_bn[10 + tid] = beta[tid] - (float)mu * sc;
    }
}

// ---------------- BN affine + relu + layer2 + sum over 54 ----------------
__global__ __launch_bounds__(256) void outK(const float* __restrict__ W2,
                                            const float* __restrict__ b2,
                                            float* __restrict__ out) {
    __shared__ float sa[10], sb[10], sW2[100], sb2[10];
    int tid = threadIdx.x;
    if (tid < 10) { sa[tid] = d_bn[tid]; sb[tid] = d_bn[10 + tid]; sb2[tid] = b2[tid]; }
    if (tid < 100) sW2[tid] = W2[tid];
    __syncthreads();

    int p = blockIdx.x * blockDim.x + tid;
    float acc[10];
#pragma unroll
    for (int c = 0; c < 10; c++) acc[c] = 0.0f;
    for (int t = 0; t < 54; t++) {
#pragma unroll
        for (int c = 0; c < 10; c++) {
            float v = d_h[(size_t)(t * 10 + c) * N_PTS + p] * sa[c] + sb[c];
            v = fmaxf(v, 0.0f);
            acc[c] += v;
        }
    }
#pragma unroll
    for (int c = 0; c < 10; c++) {
        float o = 54.0f * sb2[c];
#pragma unroll
        for (int j = 0; j < 10; j++) o += acc[j] * sW2[c * 10 + j];
        out[p * 10 + c] = o;
    }
}

// ---------------- launch ----------------
extern "C" void kernel_launch(void* const* d_in, const int* in_sizes, int n_in,
                              void* d_out, int out_size) {
    const float* center = (const float*)d_in[0];
    const float* W1 = (const float*)d_in[2];
    const float* b1 = (const float*)d_in[3];
    const float* gamma = (const float*)d_in[4];
    const float* beta = (const float*)d_in[5];
    const float* W2 = (const float*)d_in[6];
    const float* b2 = (const float*)d_in[7];
    float* out = (float*)d_out;

    void* cntPtr = nullptr;
    cudaGetSymbolAddress(&cntPtr, d_cnt);
    cudaMemsetAsync(cntPtr, 0, NCELL * sizeof(int), 0);   // memset node, not a kernel

    countK<<<256, 256>>>(center);
    scanK<<<1, 1024>>>();
    scatterK<<<256, 256>>>(center);
    knnK<<<1024, 64>>>();                                  // 4th kernel launch -> ncu slot
    featK<<<FBLK, 64>>>(center, W1, b1);
    bnK<<<1, 640>>>(gamma, beta);
    outK<<<256, 256>>>(W2, b2, out);
}

// round 7
// speedup vs baseline: 1.8871x; 1.3476x over previous
#include <cuda_runtime.h>
#include <math_constants.h>

#define N_PTS 65536
#define KNNK 54
#define GRIDD 16
#define NCELL 4096
#define CELLH 0.0625f
#define MBLK 256     // mlpK: 256 blocks x 256 threads

#define TWO_PI_F 6.28318530717958647692f
#define PI_F     3.14159265358979323846f
#define SQRT3_F  1.73205080756887729353f

// ---------------- scratch (static device memory; no allocation) ----------------
__device__ float4 d_sorted[N_PTS];
__device__ int d_cellStart[NCELL + 1];
__device__ int d_cellPtr[NCELL];
__device__ int d_cnt[NCELL];
__device__ unsigned long long d_key[KNNK * N_PTS];  // transposed: [slot][point]
__device__ int d_idx[KNNK * N_PTS];                 // sorted neighbor ids [slot][point]
__device__ float d_h[N_PTS * KNNK * 10];            // transposed: [ch][p]
__device__ float d_part[MBLK * 20];
__device__ float d_bn[20];

// canonical (+,+,+) octant: 27 cell offsets sorted by min box distance
__constant__ char4 c_ord[27] = {
    { 0, 0, 0, 0},
    { 1, 0, 0, 0}, { 0, 1, 0, 0}, { 0, 0, 1, 0},
    { 1, 1, 0, 0}, { 1, 0, 1, 0}, { 0, 1, 1, 0},
    { 1, 1, 1, 0},
    {-1, 0, 0, 0}, { 0,-1, 0, 0}, { 0, 0,-1, 0},
    {-1, 1, 0, 0}, {-1, 0, 1, 0}, { 1,-1, 0, 0},
    { 0,-1, 1, 0}, { 1, 0,-1, 0}, { 0, 1,-1, 0},
    {-1, 1, 1, 0}, { 1,-1, 1, 0}, { 1, 1,-1, 0},
    {-1,-1, 0, 0}, {-1, 0,-1, 0}, { 0,-1,-1, 0},
    {-1,-1, 1, 0}, {-1, 1,-1, 0}, { 1,-1,-1, 0},
    {-1,-1,-1, 0}
};

__device__ __forceinline__ int cellCoord(float v) {
    int c = (int)floorf(v * 16.0f);
    c = c < 0 ? 0 : c;
    return c > (GRIDD - 1) ? (GRIDD - 1) : c;
}

__device__ __forceinline__ float sumsq_rn(float x, float y, float z) {
    return __fadd_rn(__fadd_rn(__fmul_rn(x, x), __fmul_rn(y, y)), __fmul_rn(z, z));
}

__device__ __forceinline__ float dot3_fma(float ax, float ay, float az,
                                          float bx, float by, float bz) {
    return __fmaf_rn(az, bz, __fmaf_rn(ay, by, __fmul_rn(ax, bx)));
}

__device__ __forceinline__ unsigned mapf(float d) {
    unsigned u = __float_as_uint(d);
    return (u & 0x80000000u) ? ~u : (u | 0x80000000u);
}
__device__ __forceinline__ float unmapf(unsigned m) {
    unsigned u = (m & 0x80000000u) ? (m & 0x7FFFFFFFu) : ~m;
    return __uint_as_float(u);
}

// ---------------- grid build ----------------
__global__ void countK(const float* __restrict__ c) {
    int i = blockIdx.x * blockDim.x + threadIdx.x;
    if (i >= N_PTS) return;
    int cx = cellCoord(c[3 * i]);
    int cy = cellCoord(c[3 * i + 1]);
    int cz = cellCoord(c[3 * i + 2]);
    atomicAdd(&d_cnt[(cz * GRIDD + cy) * GRIDD + cx], 1);
}

__global__ __launch_bounds__(1024) void scanK() {
    __shared__ int s[1024];
    int t = threadIdx.x;
    int v0 = d_cnt[4 * t], v1 = d_cnt[4 * t + 1], v2 = d_cnt[4 * t + 2], v3 = d_cnt[4 * t + 3];
    int tot = v0 + v1 + v2 + v3;
    s[t] = tot;
    __syncthreads();
    for (int off = 1; off < 1024; off <<= 1) {
        int x = (t >= off) ? s[t - off] : 0;
        __syncthreads();
        s[t] += x;
        __syncthreads();
    }
    int excl = s[t] - tot;
    d_cellStart[4 * t] = excl;
    d_cellStart[4 * t + 1] = excl + v0;
    d_cellStart[4 * t + 2] = excl + v0 + v1;
    d_cellStart[4 * t + 3] = excl + v0 + v1 + v2;
    d_cellPtr[4 * t] = excl;
    d_cellPtr[4 * t + 1] = excl + v0;
    d_cellPtr[4 * t + 2] = excl + v0 + v1;
    d_cellPtr[4 * t + 3] = excl + v0 + v1 + v2;
    if (t == 1023) d_cellStart[NCELL] = s[1023];
}

__global__ void scatterK(const float* __restrict__ c) {
    int i = blockIdx.x * blockDim.x + threadIdx.x;
    if (i >= N_PTS) return;
    float x = c[3 * i], y = c[3 * i + 1], z = c[3 * i + 2];
    int cid = (cellCoord(z) * GRIDD + cellCoord(y)) * GRIDD + cellCoord(x);
    int pos = atomicAdd(&d_cellPtr[cid], 1);
    d_sorted[pos] = make_float4(x, y, z, __int_as_float(i));
}

// ---------------- KNN: smem top-54 with 9-group hierarchical worst tracker ----------------
__global__ __launch_bounds__(64, 8) void knnK() {
    __shared__ unsigned long long sKV[KNNK * 64];
    int tid = threadIdx.x;
    int t = blockIdx.x * 64 + tid;
    float4 q = d_sorted[t];
    int qi = __float_as_int(q.w);
    float qx = q.x, qy = q.y, qz = q.z;
    float qsq = sumsq_rn(qx, qy, qz);
    int cx = cellCoord(qx), cy = cellCoord(qy), cz = cellCoord(qz);

    int count = 0;
    unsigned long long gm[9];               // group maxima (6 slots each)
    unsigned long long wkey = 0xFFFFFFFFFFFFFFFFull;
    float worst_d = CUDART_INF_F;

    auto processCell = [&](int cid) {
        int s = d_cellStart[cid], e = d_cellStart[cid + 1];
        for (int p = s; p < e; p++) {
            float4 pt = d_sorted[p];
            float psq = sumsq_rn(pt.x, pt.y, pt.z);
            float dot = dot3_fma(qx, qy, qz, pt.x, pt.y, pt.z);
            float d = __fsub_rn(__fadd_rn(qsq, psq), __fmul_rn(2.0f, dot));
            unsigned pi = __float_as_uint(pt.w);
            unsigned long long nk = ((unsigned long long)mapf(d) << 32) | pi;
            if (count < KNNK) {
                sKV[count * 64 + tid] = nk;
                count++;
                if (count == KNNK) {
                    unsigned long long w = 0ULL;
#pragma unroll
                    for (int g = 0; g < 9; g++) {
                        unsigned long long gv = 0ULL;
#pragma unroll
                        for (int j = 0; j < 6; j++) {
                            unsigned long long v = sKV[(g * 6 + j) * 64 + tid];
                            if (v > gv) gv = v;
                        }
                        gm[g] = gv;
                        if (gv > w) w = gv;
                    }
                    wkey = w;
                    worst_d = unmapf((unsigned)(w >> 32));
                }
            } else if (nk < wkey) {
                // worst group
                int gw = 0;
                unsigned long long gv = gm[0];
#pragma unroll
                for (int g = 1; g < 9; g++) if (gm[g] > gv) { gv = gm[g]; gw = g; }
                // scan that group: max slot + 2nd max
                int base = gw * 6;
                unsigned long long m1 = 0ULL, m2 = 0ULL;
                int ms = base;
#pragma unroll
                for (int j = 0; j < 6; j++) {
                    unsigned long long v = sKV[(base + j) * 64 + tid];
                    if (v > m1) { m2 = m1; m1 = v; ms = base + j; }
                    else if (v > m2) m2 = v;
                }
                sKV[ms * 64 + tid] = nk;
                gm[gw] = nk > m2 ? nk : m2;
                // new global worst
                unsigned long long w = gm[0];
#pragma unroll
                for (int g = 1; g < 9; g++) if (gm[g] > w) w = gm[g];
                wkey = w;
                worst_d = unmapf((unsigned)(w >> 32));
            }
        }
    };

    // octant signs: near side first in canonical order
    int sx = (qx > ((float)cx + 0.5f) * CELLH) ? 1 : -1;
    int sy = (qy > ((float)cy + 0.5f) * CELLH) ? 1 : -1;
    int sz = (qz > ((float)cz + 0.5f) * CELLH) ? 1 : -1;

    // phase 1: 27 cells (m<=1) in approximate box-distance order
#pragma unroll 1
    for (int o = 0; o < 27; o++) {
        char4 c = c_ord[o];
        int x = cx + sx * (int)c.x;
        int y = cy + sy * (int)c.y;
        int z = cz + sz * (int)c.z;
        if (((unsigned)x | (unsigned)y | (unsigned)z) > 15u) continue;
        float dxx = fmaxf(0.0f, fmaxf((float)x * CELLH - qx, qx - ((float)x * CELLH + CELLH)));
        float dyy = fmaxf(0.0f, fmaxf((float)y * CELLH - qy, qy - ((float)y * CELLH + CELLH)));
        float dzz = fmaxf(0.0f, fmaxf((float)z * CELLH - qz, qz - ((float)z * CELLH + CELLH)));
        if (dxx * dxx + dyy * dyy + dzz * dzz > worst_d + 4e-6f) continue;
        processCell((z * GRIDD + y) * GRIDD + x);
    }

    // gap to the region outside the 3x3x3 cube
    {
        float g = CUDART_INF_F;
        if (cx - 1 > 0)         g = fminf(g, qx - (float)(cx - 1) * CELLH);
        if (cx + 1 < GRIDD - 1) g = fminf(g, (float)(cx + 2) * CELLH - qx);
        if (cy - 1 > 0)         g = fminf(g, qy - (float)(cy - 1) * CELLH);
        if (cy + 1 < GRIDD - 1) g = fminf(g, (float)(cy + 2) * CELLH - qy);
        if (cz - 1 > 0)         g = fminf(g, qz - (float)(cz - 1) * CELLH);
        if (cz + 1 < GRIDD - 1) g = fminf(g, (float)(cz + 2) * CELLH - qz);
        if (worst_d + 4e-6f < g * g) goto done;
    }

    // phase 2: rings m >= 2 (rare)
    {
        int maxm = cx; if (GRIDD - 1 - cx > maxm) maxm = GRIDD - 1 - cx;
        if (cy > maxm) maxm = cy; if (GRIDD - 1 - cy > maxm) maxm = GRIDD - 1 - cy;
        if (cz > maxm) maxm = cz; if (GRIDD - 1 - cz > maxm) maxm = GRIDD - 1 - cz;

        for (int m = 2; m <= maxm; m++) {
            int zlo = cz - m < 0 ? 0 : cz - m;
            int zhi = cz + m > GRIDD - 1 ? GRIDD - 1 : cz + m;
            for (int z = zlo; z <= zhi; z++) {
                int adz = z - cz; adz = adz < 0 ? -adz : adz;
                float lo = (float)z * CELLH, hi = lo + CELLH;
                float dz = fmaxf(0.0f, fmaxf(lo - qz, qz - hi));
                float dz2 = dz * dz;
                int ylo = cy - m < 0 ? 0 : cy - m;
                int yhi = cy + m > GRIDD - 1 ? GRIDD - 1 : cy + m;
                for (int y = ylo; y <= yhi; y++) {
                    int ady = y - cy; ady = ady < 0 ? -ady : ady;
                    float lyo = (float)y * CELLH, lyh = lyo + CELLH;
                    float dy = fmaxf(0.0f, fmaxf(lyo - qy, qy - lyh));
                    float dyz2 = dz2 + dy * dy;
                    if (dyz2 > worst_d + 4e-6f) continue;
                    int xlo = cx - m < 0 ? 0 : cx - m;
                    int xhi = cx + m > GRIDD - 1 ? GRIDD - 1 : cx + m;
                    for (int x = xlo; x <= xhi; x++) {
                        int adx = x - cx; adx = adx < 0 ? -adx : adx;
                        int cheb = adx > ady ? adx : ady;
                        if (adz > cheb) cheb = adz;
                        if (cheb != m) continue;
                        float lxo = (float)x * CELLH, lxh = lxo + CELLH;
                        float dx = fmaxf(0.0f, fmaxf(lxo - qx, qx - lxh));
                        if (dyz2 + dx * dx > worst_d + 4e-6f) continue;
                        processCell((z * GRIDD + y) * GRIDD + x);
                    }
                }
            }
            float g = CUDART_INF_F;
            if (cx - m > 0)         g = fminf(g, qx - (float)(cx - m) * CELLH);
            if (cx + m < GRIDD - 1) g = fminf(g, (float)(cx + m + 1) * CELLH - qx);
            if (cy - m > 0)         g = fminf(g, qy - (float)(cy - m) * CELLH);
            if (cy + m < GRIDD - 1) g = fminf(g, (float)(cy + m + 1) * CELLH - qy);
            if (cz - m > 0)         g = fminf(g, qz - (float)(cz - m) * CELLH);
            if (cz + m < GRIDD - 1) g = fminf(g, (float)(cz + m + 1) * CELLH - qz);
            if (worst_d + 4e-6f < g * g) break;
        }
    }

done:
#pragma unroll
    for (int j = 0; j < KNNK; j++) d_key[(size_t)j * N_PTS + qi] = sKV[j * 64 + tid];
}

// ---------------- sortK: rho-sort + segmented phi-sort -> sorted neighbor ids ----------------
__global__ __launch_bounds__(64) void sortK(const float* __restrict__ cen) {
    __shared__ float sRho[54 * 64];
    __shared__ float sPhi[54 * 64];
    __shared__ unsigned char sPermA[54 * 64];
    unsigned char* sPermB = (unsigned char*)sRho;   // rho dead after rho-rank

    int tid = threadIdx.x;
    int p = blockIdx.x * 64 + tid;
    float qx = cen[3 * p], qy = cen[3 * p + 1], qz = cen[3 * p + 2];

    auto keyAt = [&](int i) -> unsigned long long {
        return d_key[(size_t)i * N_PTS + p];   // coalesced across lanes
    };

    for (int j = 0; j < 54; j++) {
        int nb = (int)(keyAt(j) & 0xFFFFFFFFull);
        float x = __fsub_rn(cen[3 * nb], qx);
        float y = __fsub_rn(cen[3 * nb + 1], qy);
        float z = __fsub_rn(cen[3 * nb + 2], qz);
        float rx = __fmaf_rn(z, -0.5f,    __fmaf_rn(y, 0.7071f, __fmul_rn(x,  0.5f)));
        float ry = __fmaf_rn(z,  0.5f,    __fmaf_rn(y, 0.7071f, __fmul_rn(x, -0.5f)));
        float rz = __fmaf_rn(z,  0.7071f, __fmul_rn(x, 0.7071f));
        sRho[j * 64 + tid] = __fsqrt_rn(sumsq_rn(rx, ry, rz));
        sPhi[j * 64 + tid] = __fadd_rn(__fdiv_rn(atan2f(ry, rx), TWO_PI_F), 0.5f);
    }

    // rho rank-sort; lex(rho, key64) == stable rho-sort of (d,idx)-ascending order
    for (int j = 0; j < 54; j++) {
        float kj = sRho[j * 64 + tid];
        int r = 0;
#pragma unroll
        for (int i = 0; i < 54; i++) {
            float ki = sRho[i * 64 + tid];
            if (ki < kj) r++;
            else if (ki == kj && i != j && keyAt(i) < keyAt(j)) r++;   // rare tie
        }
        sPermA[r * 64 + tid] = (unsigned char)j;
    }

    // stable phi rank-sort within segments [0,9) [9,27) [27,54)
#define PHI_SEG(A, B)                                                        \
    for (int pos = (A); pos < (B); pos++) {                                  \
        int sl = sPermA[pos * 64 + tid];                                     \
        float kp = sPhi[sl * 64 + tid];                                      \
        int r = 0;                                                           \
        _Pragma("unroll")                                                    \
        for (int i = (A); i < (B); i++) {                                    \
            int si = sPermA[i * 64 + tid];                                   \
            float ki = sPhi[si * 64 + tid];                                  \
            r += (ki < kp || (ki == kp && i < pos)) ? 1 : 0;                 \
        }                                                                    \
        sPermB[((A) + r) * 64 + tid] = (unsigned char)sl;                    \
    }
    PHI_SEG(0, 9)
    PHI_SEG(9, 27)
    PHI_SEG(27, 54)
#undef PHI_SEG

    // write sorted neighbor ids, coalesced
#pragma unroll
    for (int t = 0; t < 54; t++) {
        int sl = sPermB[t * 64 + tid];
        d_idx[(size_t)t * N_PTS + p] = (int)(keyAt(sl) & 0xFFFFFFFFull);
    }
}

// ---------------- mlpK: triangles + layer1 + BN partial sums ----------------
__global__ __launch_bounds__(256) void mlpK(const float* __restrict__ cen,
                                            const float* __restrict__ W1,
                                            const float* __restrict__ b1) {
    __shared__ float sW1[100], sb1[10];
    __shared__ float sWS[8][20];
    int tid = threadIdx.x;
    if (tid < 100) sW1[tid] = W1[tid];
    if (tid < 10) sb1[tid] = b1[tid];
    __syncthreads();

    int p = blockIdx.x * 256 + tid;
    float qx = cen[3 * p], qy = cen[3 * p + 1], qz = cen[3 * p + 2];

    auto idxAt = [&](int i) -> int { return d_idx[(size_t)i * N_PTS + p]; };
    auto nextT = [](int t) -> int {
        int base, len;
        if (t < 9) { base = 0; len = 9; }
        else if (t < 27) { base = 9; len = 18; }
        else { base = 27; len = 27; }
        int loc = t - base + 1;
        return base + (loc == len ? 0 : loc);
    };

    // pre-pass: cross-product only -> bad mask, pm, first good triangle
    unsigned long long badm = 0ULL;
    float pm = 1.0f;
    int first = -1;
    for (int t = 0; t < 54; t++) {
        int na = idxAt(t), nb = idxAt(nextT(t));
        float e1x = __fsub_rn(cen[3 * na], qx);
        float e1y = __fsub_rn(cen[3 * na + 1], qy);
        float e1z = __fsub_rn(cen[3 * na + 2], qz);
        float e2x = __fsub_rn(cen[3 * nb], qx);
        float e2y = __fsub_rn(cen[3 * nb + 1], qy);
        float e2z = __fsub_rn(cen[3 * nb + 2], qz);
        float nx = __fsub_rn(__fmul_rn(e1y, e2z), __fmul_rn(e1z, e2y));
        float ny = __fsub_rn(__fmul_rn(e1z, e2x), __fmul_rn(e1x, e2z));
        float nz = __fsub_rn(__fmul_rn(e1x, e2y), __fmul_rn(e1y, e2x));
        float nl = __fsqrt_rn(sumsq_rn(nx, ny, nz));
        bool bad = (nl == 0.0f);
        if (t == 0) {
            float ux = bad ? 0.0f : __fdiv_rn(nx, nl);
            pm = (ux > 0.0f) ? 1.0f : -1.0f;
        }
        if (bad) badm |= (1ULL << t);
        else if (first < 0) first = t;
    }
    if (first < 0) first = 0;

    auto evalTri = [&](int t, float& ux, float& uy, float& uz,
                       float& ccx, float& ccy, float& ccz, float& pos) {
        int na = idxAt(t), nb = idxAt(nextT(t));
        float e1x = __fsub_rn(cen[3 * na], qx);
        float e1y = __fsub_rn(cen[3 * na + 1], qy);
        float e1z = __fsub_rn(cen[3 * na + 2], qz);
        float e2x = __fsub_rn(cen[3 * nb], qx);
        float e2y = __fsub_rn(cen[3 * nb + 1], qy);
        float e2z = __fsub_rn(cen[3 * nb + 2], qz);
        float nx = __fsub_rn(__fmul_rn(e1y, e2z), __fmul_rn(e1z, e2y));
        float ny = __fsub_rn(__fmul_rn(e1z, e2x), __fmul_rn(e1x, e2z));
        float nz = __fsub_rn(__fmul_rn(e1x, e2y), __fmul_rn(e1y, e2x));
        float nl = __fsqrt_rn(sumsq_rn(nx, ny, nz));
        bool bad = (nl == 0.0f);
        if (bad) { ux = 0.0f; uy = 0.0f; uz = 0.0f; }
        else {
            ux = __fdiv_rn(nx, nl); uy = __fdiv_rn(ny, nl); uz = __fdiv_rn(nz, nl);
        }
        ux = __fmul_rn(ux, pm); uy = __fmul_rn(uy, pm); uz = __fmul_rn(uz, pm);
        ccx = __fdiv_rn(__fadd_rn(e1x, e2x), 3.0f);
        ccy = __fdiv_rn(__fadd_rn(e1y, e2y), 3.0f);
        ccz = __fdiv_rn(__fadd_rn(e1z, e2z), 3.0f);
        pos = __fdiv_rn(
            __fadd_rn(__fadd_rn(__fmul_rn(ux, ccx), __fmul_rn(uy, ccy)), __fmul_rn(uz, ccz)),
            SQRT3_F);
    };

    float fux, fuy, fuz, fcx, fcy, fcz, fpos;
    evalTri(first, fux, fuy, fuz, fcx, fcy, fcz, fpos);

    float s0[10], s1[10];
#pragma unroll
    for (int c = 0; c < 10; c++) { s0[c] = 0.0f; s1[c] = 0.0f; }

    for (int t = 0; t < 54; t++) {
        float ux, uy, uz, ccx, ccy, ccz, pos;
        evalTri(t, ux, uy, uz, ccx, ccy, ccz, pos);
        bool bad = ((badm >> t) & 1ULL) != 0ULL;

        float rho = __fsqrt_rn(sumsq_rn(ccx, ccy, ccz));
        float phi = __fadd_rn(__fdiv_rn(atan2f(ccy, ccx), TWO_PI_F), 0.5f);
        float theta;
        if (rho == 0.0f) theta = 0.0f;
        else {
            float r = __fdiv_rn(ccz, rho);
            r = fminf(1.0f, fmaxf(-1.0f, r));
            theta = __fdiv_rn(acosf(r), PI_F);
        }
        float f[10];
        f[0] = rho; f[1] = theta; f[2] = phi;
        f[3] = bad ? fux : ux; f[4] = bad ? fuy : uy; f[5] = bad ? fuz : uz;
        f[6] = bad ? fpos : pos;
        f[7] = bad ? fcx : ccx; f[8] = bad ? fcy : ccy; f[9] = bad ? fcz : ccz;

        int chBase = t * 10;
#pragma unroll
        for (int c = 0; c < 10; c++) {
            float acc = 0.0f;
#pragma unroll
            for (int k = 0; k < 10; k++) acc += f[k] * sW1[c * 10 + k];
            float h = acc + sb1[c];
            d_h[(size_t)(chBase + c) * N_PTS + p] = h;   // coalesced
            s0[c] += h;
            s1[c] += h * h;
        }
    }

    // block reduction: per-warp shuffle, then 8-way cross-warp sum
    int lane = tid & 31, wrp = tid >> 5;
#pragma unroll
    for (int v = 0; v < 20; v++) {
        float a = (v < 10) ? s0[v] : s1[v - 10];
#pragma unroll
        for (int off = 16; off > 0; off >>= 1) a += __shfl_down_sync(0xFFFFFFFFu, a, off);
        if (lane == 0) sWS[wrp][v] = a;
    }
    __syncthreads();
    if (tid < 20) {
        float a = 0.0f;
#pragma unroll
        for (int w = 0; w < 8; w++) a += sWS[w][tid];
        d_part[blockIdx.x * 20 + tid] = a;
    }
}

// ---------------- BN finalize ----------------
__global__ __launch_bounds__(640) void bnK(const float* __restrict__ gamma,
                                           const float* __restrict__ beta) {
    __shared__ float S[20];
    int tid = threadIdx.x;
    int w = tid / 32, l = tid % 32;
    float a = 0.0f;
    for (int k = l; k < MBLK; k += 32) a += d_part[k * 20 + w];
#pragma unroll
    for (int off = 16; off > 0; off >>= 1) a += __shfl_down_sync(0xFFFFFFFFu, a, off);
    if (l == 0) S[w] = a;
    __syncthreads();
    if (tid < 10) {
        const double M = (double)N_PTS * 54.0;
        double mu = (double)S[tid] / M;
        double var = (double)S[tid + 10] / M - mu * mu;
        if (var < 0.0) var = 0.0;
        float sc = gamma[tid] * rsqrtf((float)var + 1e-5f);
        d_bn[tid] = sc;
        d_bn[10 + tid] = beta[tid] - (float)mu * sc;
    }
}

// ---------------- BN affine + relu + layer2 + sum over 54 ----------------
__global__ __launch_bounds__(256) void outK(const float* __restrict__ W2,
                                            const float* __restrict__ b2,
                                            float* __restrict__ out) {
    __shared__ float sa[10], sb[10], sW2[100], sb2[10];
    int tid = threadIdx.x;
    if (tid < 10) { sa[tid] = d_bn[tid]; sb[tid] = d_bn[10 + tid]; sb2[tid] = b2[tid]; }
    if (tid < 100) sW2[tid] = W2[tid];
    __syncthreads();

    int p = blockIdx.x * blockDim.x + tid;
    float acc[10];
#pragma unroll
    for (int c = 0; c < 10; c++) acc[c] = 0.0f;
    for (int t = 0; t < 54; t++) {
#pragma unroll
        for (int c = 0; c < 10; c++) {
            float v = d_h[(size_t)(t * 10 + c) * N_PTS + p] * sa[c] + sb[c];
            v = fmaxf(v, 0.0f);
            acc[c] += v;
        }
    }
#pragma unroll
    for (int c = 0; c < 10; c++) {
        float o = 54.0f * sb2[c];
#pragma unroll
        for (int j = 0; j < 10; j++) o += acc[j] * sW2[c * 10 + j];
        out[p * 10 + c] = o;
    }
}

// ---------------- launch ----------------
extern "C" void kernel_launch(void* const* d_in, const int* in_sizes, int n_in,
                              void* d_out, int out_size) {
    const float* center = (const float*)d_in[0];
    const float* W1 = (const float*)d_in[2];
    const float* b1 = (const float*)d_in[3];
    const float* gamma = (const float*)d_in[4];
    const float* beta = (const float*)d_in[5];
    const float* W2 = (const float*)d_in[6];
    const float* b2 = (const float*)d_in[7];
    float* out = (float*)d_out;

    void* cntPtr = nullptr;
    cudaGetSymbolAddress(&cntPtr, d_cnt);
    cudaMemsetAsync(cntPtr, 0, NCELL * sizeof(int), 0);

    countK<<<256, 256>>>(center);
    scanK<<<1, 1024>>>();
    scatterK<<<256, 256>>>(center);
    knnK<<<1024, 64>>>();                 // 4th kernel launch -> ncu slot
    sortK<<<1024, 64>>>(center);
    mlpK<<<MBLK, 256>>>(center, W1, b1);
    bnK<<<1, 640>>>(gamma, beta);
    outK<<<256, 256>>>(W2, b2, out);
}